// round 1
// baseline (speedup 1.0000x reference)
#include <cuda_runtime.h>
#include <cuda_bf16.h>
#include <cstdint>

// Problem constants
#define SEG    2048          // SEG_LEN
#define DHEAD  1024          // model dim
#define NSEGS  8             // B(2) * n_seg(4)

// Scratch: full rate-1 score matrix per (b,seg). Rates 2/4/8 are strided subsets.
// 8 * 2048 * 2048 floats = 134 MB.
__device__ float g_scores[(size_t)NSEGS * SEG * SEG];

// ---------------------------------------------------------------------------
// Phase 1: scores[z][q][k] = sum_d Q[z][q][d] * K[z][k][d]
// Classic 128x128x8 fp32 SGEMM (NT layout: both operands d-contiguous).
// ---------------------------------------------------------------------------
__global__ __launch_bounds__(256, 2)
void qk_kernel(const float* __restrict__ Q, const float* __restrict__ K)
{
    __shared__ float As[8 * 132];   // [k][m], padded row stride 132 (16B-aligned)
    __shared__ float Bs[8 * 132];   // [k][n]

    const int zi = blockIdx.z;
    const float* A  = Q + (size_t)zi * SEG * DHEAD;
    const float* Bm = K + (size_t)zi * SEG * DHEAD;
    float*       C  = g_scores + (size_t)zi * SEG * SEG;

    const int t       = threadIdx.x;         // 0..255
    const int loadRow = t >> 1;              // 0..127
    const int loadCol = (t & 1) * 4;         // 0 or 4
    const int rowA    = blockIdx.y * 128 + loadRow;
    const int rowB    = blockIdx.x * 128 + loadRow;
    const float* aptr = A  + (size_t)rowA * DHEAD + loadCol;
    const float* bptr = Bm + (size_t)rowB * DHEAD + loadCol;

    const int tx = t & 15;                   // 0..15 -> N
    const int ty = t >> 4;                   // 0..15 -> M

    float acc[8][8];
#pragma unroll
    for (int i = 0; i < 8; ++i)
#pragma unroll
        for (int j = 0; j < 8; ++j) acc[i][j] = 0.0f;

    for (int kt = 0; kt < DHEAD; kt += 8) {
        const float4 a4 = *(const float4*)(aptr + kt);
        const float4 b4 = *(const float4*)(bptr + kt);
        __syncthreads();  // previous tile's compute done before overwrite
        As[(loadCol + 0) * 132 + loadRow] = a4.x;
        As[(loadCol + 1) * 132 + loadRow] = a4.y;
        As[(loadCol + 2) * 132 + loadRow] = a4.z;
        As[(loadCol + 3) * 132 + loadRow] = a4.w;
        Bs[(loadCol + 0) * 132 + loadRow] = b4.x;
        Bs[(loadCol + 1) * 132 + loadRow] = b4.y;
        Bs[(loadCol + 2) * 132 + loadRow] = b4.z;
        Bs[(loadCol + 3) * 132 + loadRow] = b4.w;
        __syncthreads();

#pragma unroll
        for (int kk = 0; kk < 8; ++kk) {
            const float4 am0 = *(const float4*)&As[kk * 132 + ty * 8];
            const float4 am1 = *(const float4*)&As[kk * 132 + ty * 8 + 4];
            const float4 bn0 = *(const float4*)&Bs[kk * 132 + tx * 8];
            const float4 bn1 = *(const float4*)&Bs[kk * 132 + tx * 8 + 4];
            const float am[8] = {am0.x, am0.y, am0.z, am0.w, am1.x, am1.y, am1.z, am1.w};
            const float bn[8] = {bn0.x, bn0.y, bn0.z, bn0.w, bn1.x, bn1.y, bn1.z, bn1.w};
#pragma unroll
            for (int i = 0; i < 8; ++i)
#pragma unroll
                for (int j = 0; j < 8; ++j)
                    acc[i][j] = fmaf(am[i], bn[j], acc[i][j]);
        }
    }

#pragma unroll
    for (int i = 0; i < 8; ++i) {
        float* crow = C + (size_t)(blockIdx.y * 128 + ty * 8 + i) * SEG
                        + blockIdx.x * 128 + tx * 8;
        float4 o0 = {acc[i][0], acc[i][1], acc[i][2], acc[i][3]};
        float4 o1 = {acc[i][4], acc[i][5], acc[i][6], acc[i][7]};
        *(float4*)(crow)     = o0;
        *(float4*)(crow + 4) = o1;
    }
}

// ---------------------------------------------------------------------------
// Phase 2: one block per output row (zi, i).
// Loads score row i once to smem; for each rate r | i: softmax over the
// stride-r subset, then sparse PV gather of keys with s > m - 18
// (dropped mass < ~3e-5; denominator uses ALL keys). Deterministic
// (prefix-sum compaction, fixed accumulation order, no global atomics).
// ---------------------------------------------------------------------------
__global__ __launch_bounds__(256)
void softmax_pv_kernel(const float* __restrict__ V, float* __restrict__ out)
{
    __shared__ float srow[SEG];       // 8 KB
    __shared__ float redbuf[8];
    __shared__ int   warp_tot[8];
    __shared__ int   warp_off[9];
    __shared__ int   selk[512];
    __shared__ float selp[512];
    __shared__ float bcast[2];        // [0]=row max, [1]=1/denom

    const int bid = blockIdx.x;
    const int i   = bid & (SEG - 1);
    const int zi  = bid >> 11;
    const int t    = threadIdx.x;
    const int lane = t & 31;
    const int wid  = t >> 5;

    const float* sr = g_scores + (size_t)zi * SEG * SEG + (size_t)i * SEG;
#pragma unroll
    for (int j = 0; j < SEG / 256; ++j) srow[t + j * 256] = sr[t + j * 256];
    __syncthreads();

    const float* Vseg = V + (size_t)zi * SEG * DHEAD;
    float4 acc = {0.f, 0.f, 0.f, 0.f};

#pragma unroll 1
    for (int ri = 0; ri < 4; ++ri) {
        const int r = 1 << ri;
        if (i & (r - 1)) break;           // divisibility is nested: once it fails, done
        const int L = SEG >> ri;

        // ---- row max over subset ----
        float m = -1e30f;
        for (int k = t; k < L; k += 256) m = fmaxf(m, srow[k << ri]);
#pragma unroll
        for (int off = 16; off; off >>= 1)
            m = fmaxf(m, __shfl_xor_sync(0xffffffffu, m, off));
        if (lane == 0) redbuf[wid] = m;
        __syncthreads();
        if (t == 0) {
            float mm = redbuf[0];
#pragma unroll
            for (int w = 1; w < 8; ++w) mm = fmaxf(mm, redbuf[w]);
            bcast[0] = mm;
        }
        __syncthreads();
        m = bcast[0];

        // ---- denom (all keys) + candidate selection (significant keys) ----
        float lsum = 0.f;
        int   nl = 0;
        float pl[8];
        int   kl[8];
        for (int k = t; k < L; k += 256) {
            const float s = srow[k << ri];
            const float e = __expf(s - m);
            lsum += e;
            if (s > m - 18.0f) { pl[nl] = e; kl[nl] = k << ri; ++nl; }
        }
        // warp-reduce denom
        float ws = lsum;
#pragma unroll
        for (int off = 16; off; off >>= 1) ws += __shfl_xor_sync(0xffffffffu, ws, off);
        // warp inclusive scan of candidate counts
        int v = nl;
#pragma unroll
        for (int off = 1; off < 32; off <<= 1) {
            int n = __shfl_up_sync(0xffffffffu, v, off);
            if (lane >= off) v += n;
        }
        if (lane == 0)  redbuf[wid]   = ws;
        if (lane == 31) warp_tot[wid] = v;
        __syncthreads();
        if (t == 0) {
            float den = redbuf[0];
#pragma unroll
            for (int w = 1; w < 8; ++w) den += redbuf[w];
            bcast[1] = 1.0f / den;
            int run = 0;
#pragma unroll
            for (int w = 0; w < 8; ++w) { warp_off[w] = run; run += warp_tot[w]; }
            warp_off[8] = run;
        }
        __syncthreads();
        const int base = warp_off[wid] + v - nl;   // deterministic exclusive offset
        for (int j = 0; j < nl; ++j) {
            const int p = base + j;
            if (p < 512) { selk[p] = kl[j]; selp[p] = pl[j]; }
        }
        __syncthreads();
        int cnt = warp_off[8];
        if (cnt > 512) cnt = 512;
        const float inv = bcast[1];

        // ---- sparse PV gather ----
        for (int idx = 0; idx < cnt; ++idx) {
            const float p = selp[idx] * inv;
            const float4 vv = ((const float4*)(Vseg + (size_t)selk[idx] * DHEAD))[t];
            acc.x = fmaf(p, vv.x, acc.x);
            acc.y = fmaf(p, vv.y, acc.y);
            acc.z = fmaf(p, vv.z, acc.z);
            acc.w = fmaf(p, vv.w, acc.w);
        }
        __syncthreads();   // before next rate reuses shared buffers
    }

    ((float4*)(out + (size_t)((size_t)zi * SEG + i) * DHEAD))[t] = acc;
}

// ---------------------------------------------------------------------------
extern "C" void kernel_launch(void* const* d_in, const int* in_sizes, int n_in,
                              void* d_out, int out_size)
{
    const float* Q = (const float*)d_in[0];
    const float* K = (const float*)d_in[1];
    const float* V = (const float*)d_in[2];
    float* out = (float*)d_out;

    dim3 g1(SEG / 128, SEG / 128, NSEGS);   // 16 x 16 x 8
    qk_kernel<<<g1, 256>>>(Q, K);

    softmax_pv_kernel<<<NSEGS * SEG, 256>>>(V, out);
}

// round 6
// speedup vs baseline: 1.8151x; 1.8151x over previous
#include <cuda_runtime.h>
#include <cuda_bf16.h>
#include <cstdint>

// Problem constants
#define SEG    2048
#define DHEAD  1024
#define NSEGS  8

// ---------------------------------------------------------------------------
// Device scratch (no allocations allowed)
// ---------------------------------------------------------------------------
__device__ float g_scores[(size_t)NSEGS * SEG * SEG];                      // 134 MB
__device__ __align__(16) __nv_bfloat16 g_qhi[(size_t)NSEGS * SEG * DHEAD]; // 33.5 MB each
__device__ __align__(16) __nv_bfloat16 g_qlo[(size_t)NSEGS * SEG * DHEAD];
__device__ __align__(16) __nv_bfloat16 g_khi[(size_t)NSEGS * SEG * DHEAD];
__device__ __align__(16) __nv_bfloat16 g_klo[(size_t)NSEGS * SEG * DHEAD];

// ---------------------------------------------------------------------------
// Helpers (baseline sm_80-class PTX only)
// ---------------------------------------------------------------------------
__device__ __forceinline__ uint32_t smem_to_u32(const void* p) {
    uint32_t a;
    asm("{ .reg .u64 t; cvta.to.shared.u64 t, %1; cvt.u32.u64 %0, t; }" : "=r"(a) : "l"(p));
    return a;
}
__device__ __forceinline__ void cp_async16(uint32_t saddr, const void* gaddr) {
    asm volatile("cp.async.cg.shared.global [%0], [%1], 16;" :: "r"(saddr), "l"(gaddr));
}
__device__ __forceinline__ void ldmatrix_x4(uint32_t& r0, uint32_t& r1, uint32_t& r2, uint32_t& r3,
                                            uint32_t addr) {
    asm volatile("ldmatrix.sync.aligned.m8n8.x4.shared.b16 {%0,%1,%2,%3}, [%4];"
                 : "=r"(r0), "=r"(r1), "=r"(r2), "=r"(r3) : "r"(addr));
}
__device__ __forceinline__ void mma16816(float& c0, float& c1, float& c2, float& c3,
                                         uint32_t a0, uint32_t a1, uint32_t a2, uint32_t a3,
                                         uint32_t b0, uint32_t b1) {
    asm volatile("mma.sync.aligned.m16n8k16.row.col.f32.bf16.bf16.f32 "
                 "{%0,%1,%2,%3}, {%4,%5,%6,%7}, {%8,%9}, {%0,%1,%2,%3};"
                 : "+f"(c0), "+f"(c1), "+f"(c2), "+f"(c3)
                 : "r"(a0), "r"(a1), "r"(a2), "r"(a3), "r"(b0), "r"(b1));
}

// ---------------------------------------------------------------------------
// Phase 0: split fp32 -> (hi, lo) bf16, plain row-major layout.
// ---------------------------------------------------------------------------
struct alignas(8) BH4 { __nv_bfloat16 v[4]; };

__global__ __launch_bounds__(256)
void split_kernel(const float* __restrict__ Q, const float* __restrict__ K)
{
    const size_t nt = (size_t)NSEGS * SEG * (DHEAD / 4);   // float4s per tensor
    size_t idx = (size_t)blockIdx.x * 256 + threadIdx.x;
    const float* src = Q;
    __nv_bfloat16* dhi = g_qhi;
    __nv_bfloat16* dlo = g_qlo;
    if (idx >= nt) { idx -= nt; src = K; dhi = g_khi; dlo = g_klo; }

    const size_t e0 = idx * 4;
    const float4 v = *(const float4*)(src + e0);
    const float f[4] = {v.x, v.y, v.z, v.w};
    BH4 h, l;
#pragma unroll
    for (int i = 0; i < 4; ++i) {
        h.v[i] = __float2bfloat16(f[i]);
        l.v[i] = __float2bfloat16(f[i] - __bfloat162float(h.v[i]));
    }
    *(BH4*)(dhi + e0) = h;
    *(BH4*)(dlo + e0) = l;
}

// ---------------------------------------------------------------------------
// Phase 1: QK^T via mma.sync m16n8k16 (bf16 hi/lo split, fp32 accum).
// CTA: 128x128 tile, 256 thr / 8 warps, warp tile 64x32 (4x4 m16n8k16).
// K loop: chunks of 16, double-buffered cp.async.
// STATIC shared memory only (48 KB exactly): no attribute opt-in needed.
// Row stride 48 B (32 data + 16 pad): ldmatrix banks 12*i mod 32 all distinct.
// ---------------------------------------------------------------------------
#define KCH        16                    // k elems per chunk
#define ROWB       48                    // padded smem row bytes (32 + 16)
#define TILE_B     (128 * ROWB)          // 6144 B per tile
#define STAGE_B    (4 * TILE_B)          // Ah, Al, Bh, Bl = 24576 B
#define QK_SMEM    (2 * STAGE_B)         // 49152 B = 48 KB static

__device__ __forceinline__ void qk_load_stage(
    uint32_t sb, const __nv_bfloat16* gAh, const __nv_bfloat16* gAl,
    const __nv_bfloat16* gBh, const __nv_bfloat16* gBl, int kc0, int r, int s)
{
    const __nv_bfloat16* srcs[4] = {gAh, gAl, gBh, gBl};
    const uint32_t soff = (uint32_t)(r * ROWB + s * 16);
#pragma unroll
    for (int tile = 0; tile < 4; ++tile) {
        cp_async16(sb + (uint32_t)tile * TILE_B + soff,
                   (const char*)(srcs[tile] + kc0 + (size_t)r * DHEAD) + s * 16);
    }
    asm volatile("cp.async.commit_group;" ::: "memory");
}

__global__ __launch_bounds__(256, 2)
void qk_mma_kernel()
{
    __shared__ char smem[QK_SMEM];
    const uint32_t sbase = smem_to_u32(smem);

    const int t    = threadIdx.x;
    const int lane = t & 31;
    const int wid  = t >> 5;
    const int mw   = (wid & 1) * 64;     // warp M offset within CTA tile
    const int nw   = (wid >> 1) * 32;    // warp N offset

    const int zi = blockIdx.z;
    const int m0 = blockIdx.y * 128;
    const int n0 = blockIdx.x * 128;

    const __nv_bfloat16* gAh = g_qhi + ((size_t)zi * SEG + m0) * DHEAD;
    const __nv_bfloat16* gAl = g_qlo + ((size_t)zi * SEG + m0) * DHEAD;
    const __nv_bfloat16* gBh = g_khi + ((size_t)zi * SEG + n0) * DHEAD;
    const __nv_bfloat16* gBl = g_klo + ((size_t)zi * SEG + n0) * DHEAD;

    // cp.async coords: 256 16B-chunks per tile (128 rows x 32 B), 1/thread/tile
    const int r_ = t >> 1, s_ = t & 1;

    // ldmatrix lane mapping: lanes 0-7 rows 0-7 k0; 8-15 rows 8-15 k0;
    // 16-23 rows 0-7 k+8; 24-31 rows 8-15 k+8.
    const int li  = lane & 7;
    const int sel = lane >> 3;
    const uint32_t laneOff = (uint32_t)((li + (sel & 1) * 8) * ROWB + (sel >> 1) * 16);

    float acc[4][4][4];
#pragma unroll
    for (int a = 0; a < 4; ++a)
#pragma unroll
        for (int b = 0; b < 4; ++b)
#pragma unroll
            for (int c = 0; c < 4; ++c) acc[a][b][c] = 0.0f;

    qk_load_stage(sbase, gAh, gAl, gBh, gBl, 0, r_, s_);

    const int NCH = DHEAD / KCH;   // 64
    for (int c = 0; c < NCH; ++c) {
        const int buf = c & 1;
        if (c + 1 < NCH) {
            __syncthreads();                  // prior compute done before overwrite
            qk_load_stage(sbase + (uint32_t)(buf ^ 1) * STAGE_B,
                          gAh, gAl, gBh, gBl, (c + 1) * KCH, r_, s_);
            asm volatile("cp.async.wait_group 1;" ::: "memory");
        } else {
            asm volatile("cp.async.wait_group 0;" ::: "memory");
        }
        __syncthreads();                      // chunk c resident block-wide

        const uint32_t sb  = sbase + (uint32_t)buf * STAGE_B;
        const uint32_t aHi = sb + 0 * TILE_B + (uint32_t)(mw * ROWB) + laneOff;
        const uint32_t aLo = sb + 1 * TILE_B + (uint32_t)(mw * ROWB) + laneOff;
        const uint32_t bHi = sb + 2 * TILE_B + (uint32_t)(nw * ROWB) + laneOff;
        const uint32_t bLo = sb + 3 * TILE_B + (uint32_t)(nw * ROWB) + laneOff;

        uint32_t A[4][4];                     // Ah frags, 4 m-tiles
#pragma unroll
        for (int mi = 0; mi < 4; ++mi)
            ldmatrix_x4(A[mi][0], A[mi][1], A[mi][2], A[mi][3],
                        aHi + (uint32_t)(mi * 16 * ROWB));
        uint32_t B[4][2];                     // Bh frags, 4 n-tiles
#pragma unroll
        for (int p = 0; p < 2; ++p) {
            uint32_t r0, r1, r2, r3;
            ldmatrix_x4(r0, r1, r2, r3, bHi + (uint32_t)(p * 16 * ROWB));
            B[p * 2 + 0][0] = r0; B[p * 2 + 0][1] = r2;   // n rows 0-7 of pair
            B[p * 2 + 1][0] = r1; B[p * 2 + 1][1] = r3;   // n rows 8-15
        }
#pragma unroll
        for (int mi = 0; mi < 4; ++mi)
#pragma unroll
            for (int ni = 0; ni < 4; ++ni)
                mma16816(acc[mi][ni][0], acc[mi][ni][1], acc[mi][ni][2], acc[mi][ni][3],
                         A[mi][0], A[mi][1], A[mi][2], A[mi][3], B[ni][0], B[ni][1]);

        uint32_t Bl[4][2];                    // Bl frags
#pragma unroll
        for (int p = 0; p < 2; ++p) {
            uint32_t r0, r1, r2, r3;
            ldmatrix_x4(r0, r1, r2, r3, bLo + (uint32_t)(p * 16 * ROWB));
            Bl[p * 2 + 0][0] = r0; Bl[p * 2 + 0][1] = r2;
            Bl[p * 2 + 1][0] = r1; Bl[p * 2 + 1][1] = r3;
        }
#pragma unroll
        for (int mi = 0; mi < 4; ++mi)
#pragma unroll
            for (int ni = 0; ni < 4; ++ni)
                mma16816(acc[mi][ni][0], acc[mi][ni][1], acc[mi][ni][2], acc[mi][ni][3],
                         A[mi][0], A[mi][1], A[mi][2], A[mi][3], Bl[ni][0], Bl[ni][1]);

#pragma unroll
        for (int mi = 0; mi < 4; ++mi)        // overwrite A with Al frags
            ldmatrix_x4(A[mi][0], A[mi][1], A[mi][2], A[mi][3],
                        aLo + (uint32_t)(mi * 16 * ROWB));
#pragma unroll
        for (int mi = 0; mi < 4; ++mi)
#pragma unroll
            for (int ni = 0; ni < 4; ++ni)
                mma16816(acc[mi][ni][0], acc[mi][ni][1], acc[mi][ni][2], acc[mi][ni][3],
                         A[mi][0], A[mi][1], A[mi][2], A[mi][3], B[ni][0], B[ni][1]);
    }

    // Epilogue: D frag lane l -> rows (l/4, l/4+8), cols 2*(l%4)..+1
    float* C = g_scores + (size_t)zi * SEG * SEG;
    const int rl = lane >> 2;
    const int cl = (lane & 3) * 2;
#pragma unroll
    for (int mi = 0; mi < 4; ++mi) {
        const int row = m0 + mw + mi * 16 + rl;
#pragma unroll
        for (int ni = 0; ni < 4; ++ni) {
            const int col = n0 + nw + ni * 8 + cl;
            *(float2*)(C + (size_t)row * SEG + col)       = make_float2(acc[mi][ni][0], acc[mi][ni][1]);
            *(float2*)(C + (size_t)(row + 8) * SEG + col) = make_float2(acc[mi][ni][2], acc[mi][ni][3]);
        }
    }
}

// ---------------------------------------------------------------------------
// Phase 2: softmax + sparse PV gather (unchanged, verified at rel_err 8e-8).
// ---------------------------------------------------------------------------
__global__ __launch_bounds__(256)
void softmax_pv_kernel(const float* __restrict__ V, float* __restrict__ out)
{
    __shared__ float srow[SEG];
    __shared__ float redbuf[8];
    __shared__ int   warp_tot[8];
    __shared__ int   warp_off[9];
    __shared__ int   selk[512];
    __shared__ float selp[512];
    __shared__ float bcast[2];

    const int bid = blockIdx.x;
    const int i   = bid & (SEG - 1);
    const int zi  = bid >> 11;
    const int t    = threadIdx.x;
    const int lane = t & 31;
    const int wid  = t >> 5;

    const float* sr = g_scores + (size_t)zi * SEG * SEG + (size_t)i * SEG;
#pragma unroll
    for (int j = 0; j < SEG / 256; ++j) srow[t + j * 256] = sr[t + j * 256];
    __syncthreads();

    const float* Vseg = V + (size_t)zi * SEG * DHEAD;
    float4 acc = {0.f, 0.f, 0.f, 0.f};

#pragma unroll 1
    for (int ri = 0; ri < 4; ++ri) {
        const int r = 1 << ri;
        if (i & (r - 1)) break;
        const int L = SEG >> ri;

        float m = -1e30f;
        for (int k = t; k < L; k += 256) m = fmaxf(m, srow[k << ri]);
#pragma unroll
        for (int off = 16; off; off >>= 1)
            m = fmaxf(m, __shfl_xor_sync(0xffffffffu, m, off));
        if (lane == 0) redbuf[wid] = m;
        __syncthreads();
        if (t == 0) {
            float mm = redbuf[0];
#pragma unroll
            for (int w = 1; w < 8; ++w) mm = fmaxf(mm, redbuf[w]);
            bcast[0] = mm;
        }
        __syncthreads();
        m = bcast[0];

        float lsum = 0.f;
        int   nl = 0;
        float pl[8];
        int   kl[8];
        for (int k = t; k < L; k += 256) {
            const float s = srow[k << ri];
            const float e = __expf(s - m);
            lsum += e;
            if (s > m - 18.0f) { pl[nl] = e; kl[nl] = k << ri; ++nl; }
        }
        float ws = lsum;
#pragma unroll
        for (int off = 16; off; off >>= 1) ws += __shfl_xor_sync(0xffffffffu, ws, off);
        int v = nl;
#pragma unroll
        for (int off = 1; off < 32; off <<= 1) {
            int n = __shfl_up_sync(0xffffffffu, v, off);
            if (lane >= off) v += n;
        }
        if (lane == 0)  redbuf[wid]   = ws;
        if (lane == 31) warp_tot[wid] = v;
        __syncthreads();
        if (t == 0) {
            float den = redbuf[0];
#pragma unroll
            for (int w = 1; w < 8; ++w) den += redbuf[w];
            bcast[1] = 1.0f / den;
            int run = 0;
#pragma unroll
            for (int w = 0; w < 8; ++w) { warp_off[w] = run; run += warp_tot[w]; }
            warp_off[8] = run;
        }
        __syncthreads();
        const int base = warp_off[wid] + v - nl;
        for (int j = 0; j < nl; ++j) {
            const int p = base + j;
            if (p < 512) { selk[p] = kl[j]; selp[p] = pl[j]; }
        }
        __syncthreads();
        int cnt = warp_off[8];
        if (cnt > 512) cnt = 512;
        const float inv = bcast[1];

        for (int idx = 0; idx < cnt; ++idx) {
            const float p = selp[idx] * inv;
            const float4 vv = ((const float4*)(Vseg + (size_t)selk[idx] * DHEAD))[t];
            acc.x = fmaf(p, vv.x, acc.x);
            acc.y = fmaf(p, vv.y, acc.y);
            acc.z = fmaf(p, vv.z, acc.z);
            acc.w = fmaf(p, vv.w, acc.w);
        }
        __syncthreads();
    }

    ((float4*)(out + (size_t)((size_t)zi * SEG + i) * DHEAD))[t] = acc;
}

// ---------------------------------------------------------------------------
extern "C" void kernel_launch(void* const* d_in, const int* in_sizes, int n_in,
                              void* d_out, int out_size)
{
    const float* Q = (const float*)d_in[0];
    const float* K = (const float*)d_in[1];
    const float* V = (const float*)d_in[2];
    float* out = (float*)d_out;

    const size_t nthreads = 2ull * NSEGS * SEG * (DHEAD / 4);
    split_kernel<<<(unsigned)((nthreads + 255) / 256), 256>>>(Q, K);

    dim3 g1(SEG / 128, SEG / 128, NSEGS);   // 16 x 16 x 8 = 2048 CTAs
    qk_mma_kernel<<<g1, 256>>>();

    softmax_pv_kernel<<<NSEGS * SEG, 256>>>(V, out);
}